// round 4
// baseline (speedup 1.0000x reference)
#include <cuda_runtime.h>
#include <cuda_bf16.h>
#include <math.h>
#include <stdint.h>

#define D_MODEL 1024
#define D_STATE 128
#define SEQ_LEN 4096
#define BATCH   4
#define ROWS    (BATCH * SEQ_LEN)        // 16384
#define LN_EPS  1e-3f
#define NPROJ   (3 * D_STATE)            // 384 (xs|B|C packed)

// ---------------- scratch (allocation-free: __device__ globals) ----------------
// split buffers are physical [hi | lo] with row stride 2*K
__device__ __nv_bfloat16 g_xn_sp [(size_t)ROWS * 2 * D_MODEL];
__device__ float         g_z     [(size_t)ROWS * D_MODEL];
__device__ __nv_bfloat16 g_z_sp  [(size_t)ROWS * 2 * D_MODEL];
__device__ float         g_proj  [(size_t)ROWS * NPROJ];
__device__ __nv_bfloat16 g_ysc_sp[(size_t)ROWS * 2 * D_STATE];
__device__ __nv_bfloat16 g_y1_sp [(size_t)ROWS * 2 * D_MODEL];
__device__ __nv_bfloat16 g_Win_p [(size_t)D_MODEL * 2 * D_MODEL];
__device__ __nv_bfloat16 g_Wpk_p [(size_t)NPROJ   * 2 * D_MODEL];
__device__ __nv_bfloat16 g_Wso_p [(size_t)D_MODEL * 2 * D_STATE];
__device__ __nv_bfloat16 g_Wout_p[(size_t)D_MODEL * 2 * D_MODEL];
__device__ float g_bpk[NPROJ];
__device__ float g_carry[BATCH * 64 * D_STATE];

// ---------------- helpers ----------------
__device__ __forceinline__ uint32_t cvta_smem(const void* p) {
    uint32_t a;
    asm("{ .reg .u64 t; cvta.to.shared.u64 t, %1; cvt.u32.u64 %0, t; }" : "=r"(a) : "l"(p));
    return a;
}
__device__ __forceinline__ uint32_t pack_bf2(__nv_bfloat16 a, __nv_bfloat16 b) {
    __nv_bfloat162 t; t.x = a; t.y = b;
    return *reinterpret_cast<uint32_t*>(&t);
}

// ---------------- LayerNorm -> split bf16 [hi | lo] ----------------
__global__ __launch_bounds__(256) void ln_split_kernel(
    const float* __restrict__ x, const float* __restrict__ gamma,
    const float* __restrict__ beta, __nv_bfloat16* __restrict__ outp)
{
    int row = blockIdx.x;
    int tid = threadIdx.x;
    const float4* xr = (const float4*)(x + (size_t)row * D_MODEL);
    float4 v = xr[tid];

    float s  = v.x + v.y + v.z + v.w;
    float sq = v.x*v.x + v.y*v.y + v.z*v.z + v.w*v.w;
    #pragma unroll
    for (int o = 16; o > 0; o >>= 1) {
        s  += __shfl_xor_sync(0xffffffffu, s,  o);
        sq += __shfl_xor_sync(0xffffffffu, sq, o);
    }
    __shared__ float sh_s[8], sh_q[8];
    int wid = tid >> 5, lid = tid & 31;
    if (lid == 0) { sh_s[wid] = s; sh_q[wid] = sq; }
    __syncthreads();
    if (wid == 0) {
        float a = (lid < 8) ? sh_s[lid] : 0.f;
        float b = (lid < 8) ? sh_q[lid] : 0.f;
        #pragma unroll
        for (int o = 4; o > 0; o >>= 1) {
            a += __shfl_xor_sync(0xffffffffu, a, o);
            b += __shfl_xor_sync(0xffffffffu, b, o);
        }
        if (lid == 0) { sh_s[0] = a; sh_q[0] = b; }
    }
    __syncthreads();
    float mu   = sh_s[0] * (1.0f / D_MODEL);
    float var  = sh_q[0] * (1.0f / D_MODEL) - mu * mu;
    float rstd = rsqrtf(var + LN_EPS);

    float4 gv = ((const float4*)gamma)[tid];
    float4 bv = ((const float4*)beta)[tid];
    float o0 = (v.x - mu) * rstd * gv.x + bv.x;
    float o1 = (v.y - mu) * rstd * gv.y + bv.y;
    float o2 = (v.z - mu) * rstd * gv.z + bv.z;
    float o3 = (v.w - mu) * rstd * gv.w + bv.w;

    __nv_bfloat16 h0 = __float2bfloat16(o0), h1 = __float2bfloat16(o1);
    __nv_bfloat16 h2 = __float2bfloat16(o2), h3 = __float2bfloat16(o3);
    __nv_bfloat16 l0 = __float2bfloat16(o0 - __bfloat162float(h0));
    __nv_bfloat16 l1 = __float2bfloat16(o1 - __bfloat162float(h1));
    __nv_bfloat16 l2 = __float2bfloat16(o2 - __bfloat162float(h2));
    __nv_bfloat16 l3 = __float2bfloat16(o3 - __bfloat162float(h3));

    uint2 hv = make_uint2(pack_bf2(h0, h1), pack_bf2(h2, h3));
    uint2 lv = make_uint2(pack_bf2(l0, l1), pack_bf2(l2, l3));
    __nv_bfloat16* base = outp + (size_t)row * 2 * D_MODEL + tid * 4;
    *(uint2*)(base)           = hv;
    *(uint2*)(base + D_MODEL) = lv;
}

// ---------------- weight prep: W[K,N] fp32 -> Wp[N][2K] bf16 [hi | lo] ----------------
__global__ void prep_weight(const float* __restrict__ W, __nv_bfloat16* __restrict__ Wp,
                            int K, int N)
{
    int idx = blockIdx.x * blockDim.x + threadIdx.x;
    if (idx >= K * N) return;
    int k = idx / N, n = idx % N;
    float w = W[idx];
    __nv_bfloat16 hi = __float2bfloat16(w);
    __nv_bfloat16 lo = __float2bfloat16(w - __bfloat162float(hi));
    size_t base = (size_t)n * 2 * K;
    Wp[base + k]     = hi;
    Wp[base + K + k] = lo;
}

__global__ void prep_bias(const float* __restrict__ bB, const float* __restrict__ bC,
                          float* __restrict__ bp)
{
    int i = threadIdx.x;
    bp[i] = (i < 128) ? 0.f : ((i < 256) ? bB[i - 128] : bC[i - 256]);
}

// ---------------- HMMA GEMM ----------------
// Logical K = 3*K (A:[hi|lo|hi], B:[hi|hi|lo]) synthesized from physical [hi|lo].
// CTA tile 128 x BNT, 8 warps (2 M x 4 N), warp tile 64 x (BNT/4), BK=32, 3-stage cp.async.
#define BM 128
#define BK 32
#define NSTAGE 3
#define RSB 80                                  // smem row stride bytes (40 bf16)

#define MMA_BF16(d, a, b) \
    asm volatile( \
        "mma.sync.aligned.m16n8k16.row.col.f32.bf16.bf16.f32 " \
        "{%0,%1,%2,%3}, {%4,%5,%6,%7}, {%8,%9}, {%0,%1,%2,%3};" \
        : "+f"((d)[0]), "+f"((d)[1]), "+f"((d)[2]), "+f"((d)[3]) \
        : "r"((a)[0]), "r"((a)[1]), "r"((a)[2]), "r"((a)[3]), \
          "r"((b)[0]), "r"((b)[1]))

#define LDSM_X4(r, addr) \
    asm volatile("ldmatrix.sync.aligned.m8n8.x4.shared.b16 {%0,%1,%2,%3}, [%4];" \
        : "=r"((r)[0]), "=r"((r)[1]), "=r"((r)[2]), "=r"((r)[3]) : "r"(addr))

template<int BNT, bool HAS_BIAS, bool HAS_DAUX, bool HAS_RES, bool WF32, bool WSPLIT>
__global__ __launch_bounds__(256, 1)
void gemm_tc(const __nv_bfloat16* __restrict__ A, const __nv_bfloat16* __restrict__ Bw,
             int Klog, int Nc,
             float* __restrict__ Cf, __nv_bfloat16* __restrict__ Csp,
             const float* __restrict__ bias, const float* __restrict__ dvec,
             const float* __restrict__ aux, const float* __restrict__ res)
{
    constexpr int WN  = BNT / 4;                 // warp n-width (32 or 64)
    constexpr int NT  = WN / 8;                  // n-tiles per warp
    constexpr int NG  = WN / 16;                 // B ldmatrix.x4 per ks
    constexpr int A_TILE = BM * RSB;
    constexpr int STAGE  = (BM + BNT) * RSB;

    extern __shared__ __align__(128) char smem[];
    const int tid  = threadIdx.x;
    const int warp = tid >> 5, lane = tid & 31;
    const int wm = warp & 1, wn = warp >> 1;
    const int m0 = blockIdx.y * BM, n0 = blockIdx.x * BNT;
    const uint32_t smem_base = cvta_smem(smem);

    const int K  = Klog / 3;
    const int KB = K / BK;                       // physical chunks per block
    const int NK = 3 * KB;
    const size_t row_bytes = (size_t)K * 4;      // 2K bf16
    const __nv_bfloat16* Ab = A  + (size_t)m0 * 2 * K;
    const __nv_bfloat16* Bb = Bw + (size_t)n0 * 2 * K;

    float acc[4][NT][4];
    #pragma unroll
    for (int i = 0; i < 4; i++)
        #pragma unroll
        for (int j = 0; j < NT; j++)
            #pragma unroll
            for (int e = 0; e < 4; e++) acc[i][j][e] = 0.f;

    auto load_stage = [&](int sk, int buf) {
        const uint32_t sb = smem_base + buf * STAGE;
        int lkA = (sk < 2 * KB) ? sk : sk - 2 * KB;      // A: [hi|lo|hi]
        int lkB = (sk < KB)     ? sk : sk - KB;          // B: [hi|hi|lo]
        const size_t kbA = (size_t)lkA * 64;
        const size_t kbB = (size_t)lkB * 64;
        #pragma unroll
        for (int j = 0; j < (BM * 4) / 256; j++) {
            int chunk = tid + j * 256;
            int row = chunk >> 2, cb = chunk & 3;
            const char* ga = (const char*)Ab + (size_t)row * row_bytes + kbA + cb * 16;
            uint32_t da = sb + row * RSB + cb * 16;
            asm volatile("cp.async.cg.shared.global [%0], [%1], 16;" :: "r"(da), "l"(ga));
        }
        #pragma unroll
        for (int j = 0; j < (BNT * 4) / 256; j++) {
            int chunk = tid + j * 256;
            int row = chunk >> 2, cb = chunk & 3;
            const char* gb = (const char*)Bb + (size_t)row * row_bytes + kbB + cb * 16;
            uint32_t db = sb + A_TILE + row * RSB + cb * 16;
            asm volatile("cp.async.cg.shared.global [%0], [%1], 16;" :: "r"(db), "l"(gb));
        }
        asm volatile("cp.async.commit_group;");
    };

    #pragma unroll
    for (int s = 0; s < NSTAGE - 1; s++) load_stage(s, s);

    const uint32_t lrow = (lane & 15);
    const uint32_t lkb  = (lane >> 4) * 16;

    for (int i = 0; i < NK; i++) {
        asm volatile("cp.async.wait_group 1;");
        __syncthreads();

        int nxt = i + NSTAGE - 1;
        if (nxt < NK) load_stage(nxt, nxt % NSTAGE);
        else          asm volatile("cp.async.commit_group;");

        const uint32_t sb = smem_base + (i % NSTAGE) * STAGE;
        const uint32_t abase = sb + (wm * 64) * RSB;
        const uint32_t bbase = sb + A_TILE + (wn * WN) * RSB;

        #pragma unroll
        for (int ks = 0; ks < 2; ks++) {
            uint32_t Af[4][4], Bf[NG][4];
            #pragma unroll
            for (int mt = 0; mt < 4; mt++)
                LDSM_X4(Af[mt], abase + (mt * 16 + lrow) * RSB + ks * 32 + lkb);
            #pragma unroll
            for (int g = 0; g < NG; g++)
                LDSM_X4(Bf[g], bbase + (g * 16 + lrow) * RSB + ks * 32 + lkb);

            #pragma unroll
            for (int mt = 0; mt < 4; mt++) {
                #pragma unroll
                for (int nt = 0; nt < NT; nt++) {
                    uint32_t b2[2] = { Bf[nt >> 1][nt & 1], Bf[nt >> 1][(nt & 1) + 2] };
                    MMA_BF16(acc[mt][nt], Af[mt], b2);
                }
            }
        }
    }

    // ---- epilogue in two 64-row halves (smem bounce, fused ops) ----
    constexpr int SSTR = BNT + 4;
    float* stile = (float*)smem;                 // [64][SSTR]
    const int groupID = lane >> 2, tig = lane & 3;
    constexpr int TPR = BNT / 4;                 // threads per row
    constexpr int RPI = 256 / TPR;               // rows per iteration
    const int ecol = (tid % TPR) * 4;
    const int erow = tid / TPR;
    int col = n0 + ecol;

    float4 b4 = make_float4(0.f, 0.f, 0.f, 0.f), d4 = b4;
    if (HAS_BIAS) b4 = *(const float4*)(bias + col);
    if (HAS_DAUX) d4 = *(const float4*)(dvec + col);

    #pragma unroll
    for (int half = 0; half < 2; half++) {
        __syncthreads();
        if (wm == half) {
            #pragma unroll
            for (int mt = 0; mt < 4; mt++) {
                int r0 = mt * 16 + groupID;
                #pragma unroll
                for (int nt = 0; nt < NT; nt++) {
                    int c = wn * WN + nt * 8 + tig * 2;
                    *(float2*)&stile[r0 * SSTR + c]       = make_float2(acc[mt][nt][0], acc[mt][nt][1]);
                    *(float2*)&stile[(r0 + 8) * SSTR + c] = make_float2(acc[mt][nt][2], acc[mt][nt][3]);
                }
            }
        }
        __syncthreads();

        #pragma unroll 4
        for (int it = 0; it < 64 / RPI; it++) {
            int rl = it * RPI + erow;
            int row = m0 + half * 64 + rl;
            float4 v = *(float4*)&stile[rl * SSTR + ecol];
            if (HAS_BIAS) { v.x += b4.x; v.y += b4.y; v.z += b4.z; v.w += b4.w; }
            if (HAS_DAUX) {
                float4 a4 = *(const float4*)(aux + (size_t)row * Nc + col);
                v.x += d4.x * a4.x; v.y += d4.y * a4.y; v.z += d4.z * a4.z; v.w += d4.w * a4.w;
            }
            if (HAS_RES) {
                float4 r4 = *(const float4*)(res + (size_t)row * Nc + col);
                v.x += r4.x; v.y += r4.y; v.z += r4.z; v.w += r4.w;
            }
            if (WF32) *(float4*)(Cf + (size_t)row * Nc + col) = v;
            if (WSPLIT) {
                __nv_bfloat16 h0 = __float2bfloat16(v.x), h1 = __float2bfloat16(v.y);
                __nv_bfloat16 h2 = __float2bfloat16(v.z), h3 = __float2bfloat16(v.w);
                __nv_bfloat16 l0 = __float2bfloat16(v.x - __bfloat162float(h0));
                __nv_bfloat16 l1 = __float2bfloat16(v.y - __bfloat162float(h1));
                __nv_bfloat16 l2 = __float2bfloat16(v.z - __bfloat162float(h2));
                __nv_bfloat16 l3 = __float2bfloat16(v.w - __bfloat162float(h3));
                uint2 hv = make_uint2(pack_bf2(h0, h1), pack_bf2(h2, h3));
                uint2 lv = make_uint2(pack_bf2(l0, l1), pack_bf2(l2, l3));
                __nv_bfloat16* bp = Csp + (size_t)row * 2 * Nc + col;
                *(uint2*)(bp)      = hv;
                *(uint2*)(bp + Nc) = lv;
            }
        }
    }
}

// ---------------- chunked scan (== FFT causal conv) ----------------
#define CHUNK 64
#define NCHUNK (SEQ_LEN / CHUNK)

__global__ __launch_bounds__(128) void scan1(const float* __restrict__ proj,
                                             const float* __restrict__ A_log,
                                             float* __restrict__ carry)
{
    int c = blockIdx.x, b = blockIdx.y, s = threadIdx.x;
    float lam = expf(-expf(A_log[s]));
    size_t row0 = (size_t)b * SEQ_LEN + c * CHUNK;
    float y = 0.f;
    #pragma unroll 8
    for (int t = 0; t < CHUNK; t++) {
        const float* p = proj + (row0 + t) * NPROJ;
        y = fmaf(lam, y, p[s] * p[128 + s]);
    }
    carry[(b * NCHUNK + c) * D_STATE + s] = y;
}

__global__ __launch_bounds__(128) void scan2(const float* __restrict__ A_log,
                                             float* __restrict__ carry)
{
    int b = blockIdx.x, s = threadIdx.x;
    float lam64 = expf(-expf(A_log[s]) * (float)CHUNK);
    float S = 0.f;
    for (int c = 0; c < NCHUNK; c++) {
        size_t i = (size_t)(b * NCHUNK + c) * D_STATE + s;
        float f = carry[i];
        carry[i] = S;
        S = fmaf(lam64, S, f);
    }
}

__global__ __launch_bounds__(128) void scan3(const float* __restrict__ proj,
                                             const float* __restrict__ A_log,
                                             const float* __restrict__ carry,
                                             __nv_bfloat16* __restrict__ ysp)
{
    int c = blockIdx.x, b = blockIdx.y, s = threadIdx.x;
    float lam = expf(-expf(A_log[s]));
    float y = carry[(b * NCHUNK + c) * D_STATE + s];
    size_t row0 = (size_t)b * SEQ_LEN + c * CHUNK;
    #pragma unroll 4
    for (int t = 0; t < CHUNK; t++) {
        size_t row = row0 + t;
        const float* p = proj + row * NPROJ;
        y = fmaf(lam, y, p[s] * p[128 + s]);
        float o = y * p[256 + s];
        __nv_bfloat16 hi = __float2bfloat16(o);
        __nv_bfloat16 lo = __float2bfloat16(o - __bfloat162float(hi));
        __nv_bfloat16* bp = ysp + row * 2 * D_STATE;
        bp[s]           = hi;
        bp[D_STATE + s] = lo;
    }
}

// ---------------- launch ----------------
#define GSM256 (NSTAGE * (BM + 256) * RSB)   // 92160
#define GSM128 (NSTAGE * (BM + 128) * RSB)   // 61440

extern "C" void kernel_launch(void* const* d_in, const int* in_sizes, int n_in,
                              void* d_out, int out_size)
{
    const float* x        = (const float*)d_in[0];
    const float* ln_gamma = (const float*)d_in[1];
    const float* ln_beta  = (const float*)d_in[2];
    const float* W_in     = (const float*)d_in[3];
    const float* b_in     = (const float*)d_in[4];
    const float* W_xs     = (const float*)d_in[5];
    const float* W_B      = (const float*)d_in[6];
    const float* b_B      = (const float*)d_in[7];
    const float* W_C      = (const float*)d_in[8];
    const float* b_C      = (const float*)d_in[9];
    const float* A_log    = (const float*)d_in[10];
    const float* Dv       = (const float*)d_in[11];
    const float* W_so     = (const float*)d_in[12];
    const float* W_out    = (const float*)d_in[13];
    const float* b_out    = (const float*)d_in[14];
    float* out = (float*)d_out;

    __nv_bfloat16 *p_xn_sp, *p_z_sp, *p_ysc_sp, *p_y1_sp;
    __nv_bfloat16 *p_Win, *p_Wpk, *p_Wso, *p_Wout;
    float *p_z, *p_proj, *p_bpk, *p_carry;
    cudaGetSymbolAddress((void**)&p_xn_sp,  g_xn_sp);
    cudaGetSymbolAddress((void**)&p_z,      g_z);
    cudaGetSymbolAddress((void**)&p_z_sp,   g_z_sp);
    cudaGetSymbolAddress((void**)&p_proj,   g_proj);
    cudaGetSymbolAddress((void**)&p_ysc_sp, g_ysc_sp);
    cudaGetSymbolAddress((void**)&p_y1_sp,  g_y1_sp);
    cudaGetSymbolAddress((void**)&p_Win,    g_Win_p);
    cudaGetSymbolAddress((void**)&p_Wpk,    g_Wpk_p);
    cudaGetSymbolAddress((void**)&p_Wso,    g_Wso_p);
    cudaGetSymbolAddress((void**)&p_Wout,   g_Wout_p);
    cudaGetSymbolAddress((void**)&p_bpk,    g_bpk);
    cudaGetSymbolAddress((void**)&p_carry,  g_carry);

    cudaFuncSetAttribute(gemm_tc<256, true,  false, false, true,  true >, cudaFuncAttributeMaxDynamicSharedMemorySize, GSM256);
    cudaFuncSetAttribute(gemm_tc<128, true,  false, false, true,  false>, cudaFuncAttributeMaxDynamicSharedMemorySize, GSM128);
    cudaFuncSetAttribute(gemm_tc<256, false, true,  false, false, true >, cudaFuncAttributeMaxDynamicSharedMemorySize, GSM256);
    cudaFuncSetAttribute(gemm_tc<256, true,  false, true,  true,  false>, cudaFuncAttributeMaxDynamicSharedMemorySize, GSM256);

    // ---- weight prep ([hi|lo] physical) ----
    prep_weight<<<(D_MODEL * D_MODEL + 255) / 256, 256>>>(W_in,  p_Win,  D_MODEL, D_MODEL);
    prep_weight<<<(D_MODEL * D_STATE + 255) / 256, 256>>>(W_xs,  p_Wpk,                              D_MODEL, D_STATE);
    prep_weight<<<(D_MODEL * D_STATE + 255) / 256, 256>>>(W_B,   p_Wpk + (size_t)128 * 2 * D_MODEL,  D_MODEL, D_STATE);
    prep_weight<<<(D_MODEL * D_STATE + 255) / 256, 256>>>(W_C,   p_Wpk + (size_t)256 * 2 * D_MODEL,  D_MODEL, D_STATE);
    prep_weight<<<(D_STATE * D_MODEL + 255) / 256, 256>>>(W_so,  p_Wso,  D_STATE, D_MODEL);
    prep_weight<<<(D_MODEL * D_MODEL + 255) / 256, 256>>>(W_out, p_Wout, D_MODEL, D_MODEL);
    prep_bias<<<1, NPROJ>>>(b_B, b_C, p_bpk);

    // ---- 1. LayerNorm -> split bf16 ----
    ln_split_kernel<<<ROWS, 256>>>(x, ln_gamma, ln_beta, p_xn_sp);

    // ---- 2. z = xn @ W_in + b_in (fp32 z + split z') ----
    gemm_tc<256, true, false, false, true, true><<<dim3(D_MODEL / 256, ROWS / BM), 256, GSM256>>>(
        p_xn_sp, p_Win, 3 * D_MODEL, D_MODEL, p_z, p_z_sp, b_in, nullptr, nullptr, nullptr);

    // ---- 3. packed projections: [xs | B | C] ----
    gemm_tc<128, true, false, false, true, false><<<dim3(NPROJ / 128, ROWS / BM), 256, GSM128>>>(
        p_z_sp, p_Wpk, 3 * D_MODEL, NPROJ, p_proj, nullptr, p_bpk, nullptr, nullptr, nullptr);

    // ---- 4. chunked linear recurrence (== FFT causal conv) ----
    scan1<<<dim3(NCHUNK, BATCH), 128>>>(p_proj, A_log, p_carry);
    scan2<<<BATCH, 128>>>(A_log, p_carry);
    scan3<<<dim3(NCHUNK, BATCH), 128>>>(p_proj, A_log, p_carry, p_ysc_sp);

    // ---- 5. y1 = ysc @ W_so + D*z (split only) ----
    gemm_tc<256, false, true, false, false, true><<<dim3(D_MODEL / 256, ROWS / BM), 256, GSM256>>>(
        p_ysc_sp, p_Wso, 3 * D_STATE, D_MODEL, nullptr, p_y1_sp, nullptr, Dv, p_z, nullptr);

    // ---- 6. out = y1 @ W_out + b_out + x ----
    gemm_tc<256, true, false, true, true, false><<<dim3(D_MODEL / 256, ROWS / BM), 256, GSM256>>>(
        p_y1_sp, p_Wout, 3 * D_MODEL, D_MODEL, out, nullptr, b_out, nullptr, nullptr, x);
}

// round 5
// speedup vs baseline: 1.0250x; 1.0250x over previous
#include <cuda_runtime.h>
#include <cuda_bf16.h>
#include <math.h>
#include <stdint.h>

#define D_MODEL 1024
#define D_STATE 128
#define SEQ_LEN 4096
#define BATCH   4
#define ROWS    (BATCH * SEQ_LEN)        // 16384
#define LN_EPS  1e-3f
#define NPROJ   (3 * D_STATE)            // 384 (xs|B|C packed)

// ---------------- scratch (allocation-free: __device__ globals) ----------------
// split buffers are physical [hi | lo] with row stride 2*K
__device__ __nv_bfloat16 g_xn_sp [(size_t)ROWS * 2 * D_MODEL];
__device__ float         g_z     [(size_t)ROWS * D_MODEL];
__device__ __nv_bfloat16 g_z_sp  [(size_t)ROWS * 2 * D_MODEL];
__device__ float         g_proj  [(size_t)ROWS * NPROJ];
__device__ __nv_bfloat16 g_ysc_sp[(size_t)ROWS * 2 * D_STATE];
__device__ __nv_bfloat16 g_y1_sp [(size_t)ROWS * 2 * D_MODEL];
__device__ __nv_bfloat16 g_Win_p [(size_t)D_MODEL * 2 * D_MODEL];
__device__ __nv_bfloat16 g_Wpk_p [(size_t)NPROJ   * 2 * D_MODEL];
__device__ __nv_bfloat16 g_Wso_p [(size_t)D_MODEL * 2 * D_STATE];
__device__ __nv_bfloat16 g_Wout_p[(size_t)D_MODEL * 2 * D_MODEL];
__device__ float g_bpk[NPROJ];
__device__ float g_carry[BATCH * 64 * D_STATE];

// ---------------- helpers ----------------
__device__ __forceinline__ uint32_t cvta_smem(const void* p) {
    uint32_t a;
    asm("{ .reg .u64 t; cvta.to.shared.u64 t, %1; cvt.u32.u64 %0, t; }" : "=r"(a) : "l"(p));
    return a;
}
__device__ __forceinline__ uint32_t pack_bf2(__nv_bfloat16 a, __nv_bfloat16 b) {
    __nv_bfloat162 t; t.x = a; t.y = b;
    return *reinterpret_cast<uint32_t*>(&t);
}

// ---------------- LayerNorm -> split bf16 [hi | lo] ----------------
__global__ __launch_bounds__(256) void ln_split_kernel(
    const float* __restrict__ x, const float* __restrict__ gamma,
    const float* __restrict__ beta, __nv_bfloat16* __restrict__ outp)
{
    int row = blockIdx.x;
    int tid = threadIdx.x;
    const float4* xr = (const float4*)(x + (size_t)row * D_MODEL);
    float4 v = xr[tid];

    float s  = v.x + v.y + v.z + v.w;
    float sq = v.x*v.x + v.y*v.y + v.z*v.z + v.w*v.w;
    #pragma unroll
    for (int o = 16; o > 0; o >>= 1) {
        s  += __shfl_xor_sync(0xffffffffu, s,  o);
        sq += __shfl_xor_sync(0xffffffffu, sq, o);
    }
    __shared__ float sh_s[8], sh_q[8];
    int wid = tid >> 5, lid = tid & 31;
    if (lid == 0) { sh_s[wid] = s; sh_q[wid] = sq; }
    __syncthreads();
    if (wid == 0) {
        float a = (lid < 8) ? sh_s[lid] : 0.f;
        float b = (lid < 8) ? sh_q[lid] : 0.f;
        #pragma unroll
        for (int o = 4; o > 0; o >>= 1) {
            a += __shfl_xor_sync(0xffffffffu, a, o);
            b += __shfl_xor_sync(0xffffffffu, b, o);
        }
        if (lid == 0) { sh_s[0] = a; sh_q[0] = b; }
    }
    __syncthreads();
    float mu   = sh_s[0] * (1.0f / D_MODEL);
    float var  = sh_q[0] * (1.0f / D_MODEL) - mu * mu;
    float rstd = rsqrtf(var + LN_EPS);

    float4 gv = ((const float4*)gamma)[tid];
    float4 bv = ((const float4*)beta)[tid];
    float o0 = (v.x - mu) * rstd * gv.x + bv.x;
    float o1 = (v.y - mu) * rstd * gv.y + bv.y;
    float o2 = (v.z - mu) * rstd * gv.z + bv.z;
    float o3 = (v.w - mu) * rstd * gv.w + bv.w;

    __nv_bfloat16 h0 = __float2bfloat16(o0), h1 = __float2bfloat16(o1);
    __nv_bfloat16 h2 = __float2bfloat16(o2), h3 = __float2bfloat16(o3);
    __nv_bfloat16 l0 = __float2bfloat16(o0 - __bfloat162float(h0));
    __nv_bfloat16 l1 = __float2bfloat16(o1 - __bfloat162float(h1));
    __nv_bfloat16 l2 = __float2bfloat16(o2 - __bfloat162float(h2));
    __nv_bfloat16 l3 = __float2bfloat16(o3 - __bfloat162float(h3));

    uint2 hv = make_uint2(pack_bf2(h0, h1), pack_bf2(h2, h3));
    uint2 lv = make_uint2(pack_bf2(l0, l1), pack_bf2(l2, l3));
    __nv_bfloat16* base = outp + (size_t)row * 2 * D_MODEL + tid * 4;
    *(uint2*)(base)           = hv;
    *(uint2*)(base + D_MODEL) = lv;
}

// ---------------- weight prep: W[K,N] fp32 -> Wp[N][2K] bf16 [hi | lo] ----------------
__global__ void prep_weight(const float* __restrict__ W, __nv_bfloat16* __restrict__ Wp,
                            int K, int N)
{
    int idx = blockIdx.x * blockDim.x + threadIdx.x;
    if (idx >= K * N) return;
    int k = idx / N, n = idx % N;
    float w = W[idx];
    __nv_bfloat16 hi = __float2bfloat16(w);
    __nv_bfloat16 lo = __float2bfloat16(w - __bfloat162float(hi));
    size_t base = (size_t)n * 2 * K;
    Wp[base + k]     = hi;
    Wp[base + K + k] = lo;
}

__global__ void prep_bias(const float* __restrict__ bB, const float* __restrict__ bC,
                          float* __restrict__ bp)
{
    int i = threadIdx.x;
    bp[i] = (i < 128) ? 0.f : ((i < 256) ? bB[i - 128] : bC[i - 256]);
}

// ---------------- HMMA GEMM ----------------
// Logical K = 3*K (A:[hi|lo|hi], B:[hi|hi|lo]) synthesized from physical [hi|lo].
// CTA tile 128 x BNT, 16 warps (2 M x 8 N), warp tile 64 x (BNT/8), BK=32, 4-stage cp.async.
#define BM 128
#define BK 32
#define NSTAGE 4
#define NTHR 512
#define RSB 80                                  // smem row stride bytes (40 bf16)

#define MMA_BF16(d, a, b) \
    asm volatile( \
        "mma.sync.aligned.m16n8k16.row.col.f32.bf16.bf16.f32 " \
        "{%0,%1,%2,%3}, {%4,%5,%6,%7}, {%8,%9}, {%0,%1,%2,%3};" \
        : "+f"((d)[0]), "+f"((d)[1]), "+f"((d)[2]), "+f"((d)[3]) \
        : "r"((a)[0]), "r"((a)[1]), "r"((a)[2]), "r"((a)[3]), \
          "r"((b)[0]), "r"((b)[1]))

#define LDSM_X4(r, addr) \
    asm volatile("ldmatrix.sync.aligned.m8n8.x4.shared.b16 {%0,%1,%2,%3}, [%4];" \
        : "=r"((r)[0]), "=r"((r)[1]), "=r"((r)[2]), "=r"((r)[3]) : "r"(addr))

template<int BNT, bool HAS_BIAS, bool HAS_DAUX, bool HAS_RES, bool WF32, bool WSPLIT>
__global__ __launch_bounds__(NTHR, 1)
void gemm_tc(const __nv_bfloat16* __restrict__ A, const __nv_bfloat16* __restrict__ Bw,
             int Klog, int Nc,
             float* __restrict__ Cf, __nv_bfloat16* __restrict__ Csp,
             const float* __restrict__ bias, const float* __restrict__ dvec,
             const float* __restrict__ aux, const float* __restrict__ res)
{
    constexpr int WN  = BNT / 8;                 // warp n-width (32 or 16)
    constexpr int NT  = WN / 8;                  // n-tiles per warp (4 or 2)
    constexpr int NG  = (WN + 15) / 16;          // B ldmatrix.x4 groups per ks
    constexpr int A_TILE = BM * RSB;
    constexpr int STAGE  = (BM + BNT) * RSB;

    extern __shared__ __align__(128) char smem[];
    const int tid  = threadIdx.x;
    const int warp = tid >> 5, lane = tid & 31;
    const int wm = warp & 1, wn = warp >> 1;     // 2 x 8 warp grid
    const int m0 = blockIdx.y * BM, n0 = blockIdx.x * BNT;
    const uint32_t smem_base = cvta_smem(smem);

    const int K  = Klog / 3;
    const int KB = K / BK;                       // physical chunks per block
    const int NK = 3 * KB;
    const size_t row_bytes = (size_t)K * 4;      // 2K bf16
    const __nv_bfloat16* Ab = A  + (size_t)m0 * 2 * K;
    const __nv_bfloat16* Bb = Bw + (size_t)n0 * 2 * K;

    float acc[4][NT][4];
    #pragma unroll
    for (int i = 0; i < 4; i++)
        #pragma unroll
        for (int j = 0; j < NT; j++)
            #pragma unroll
            for (int e = 0; e < 4; e++) acc[i][j][e] = 0.f;

    auto load_stage = [&](int sk, int buf) {
        const uint32_t sb = smem_base + buf * STAGE;
        int lkA = (sk < 2 * KB) ? sk : sk - 2 * KB;      // A: [hi|lo|hi]
        int lkB = (sk < KB)     ? sk : sk - KB;          // B: [hi|hi|lo]
        const size_t kbA = (size_t)lkA * 64;
        const size_t kbB = (size_t)lkB * 64;
        #pragma unroll
        for (int j = 0; j < (BM * 4 + NTHR - 1) / NTHR; j++) {
            int chunk = tid + j * NTHR;
            int row = chunk >> 2, cb = chunk & 3;
            const char* ga = (const char*)Ab + (size_t)row * row_bytes + kbA + cb * 16;
            uint32_t da = sb + row * RSB + cb * 16;
            asm volatile("cp.async.cg.shared.global [%0], [%1], 16;" :: "r"(da), "l"(ga));
        }
        #pragma unroll
        for (int j = 0; j < (BNT * 4 + NTHR - 1) / NTHR; j++) {
            int chunk = tid + j * NTHR;
            if (BNT * 4 < NTHR && chunk >= BNT * 4) break;
            int row = chunk >> 2, cb = chunk & 3;
            const char* gb = (const char*)Bb + (size_t)row * row_bytes + kbB + cb * 16;
            uint32_t db = sb + A_TILE + row * RSB + cb * 16;
            asm volatile("cp.async.cg.shared.global [%0], [%1], 16;" :: "r"(db), "l"(gb));
        }
        asm volatile("cp.async.commit_group;");
    };

    #pragma unroll
    for (int s = 0; s < NSTAGE - 1; s++) load_stage(s, s);

    const uint32_t lrow = (lane & 15);
    const uint32_t lkb  = (lane >> 4) * 16;

    for (int i = 0; i < NK; i++) {
        asm volatile("cp.async.wait_group 2;");
        __syncthreads();

        int nxt = i + NSTAGE - 1;
        if (nxt < NK) load_stage(nxt, nxt & (NSTAGE - 1));
        else          asm volatile("cp.async.commit_group;");

        const uint32_t sb = smem_base + (i & (NSTAGE - 1)) * STAGE;
        const uint32_t abase = sb + (wm * 64) * RSB;
        const uint32_t bbase = sb + A_TILE + (wn * WN) * RSB;

        #pragma unroll
        for (int ks = 0; ks < 2; ks++) {
            uint32_t Af[4][4], Bf[NG][4];
            #pragma unroll
            for (int mt = 0; mt < 4; mt++)
                LDSM_X4(Af[mt], abase + (mt * 16 + lrow) * RSB + ks * 32 + lkb);
            #pragma unroll
            for (int g = 0; g < NG; g++)
                LDSM_X4(Bf[g], bbase + (g * 16 + lrow) * RSB + ks * 32 + lkb);

            #pragma unroll
            for (int mt = 0; mt < 4; mt++) {
                #pragma unroll
                for (int nt = 0; nt < NT; nt++) {
                    uint32_t b2[2] = { Bf[nt >> 1][nt & 1], Bf[nt >> 1][(nt & 1) + 2] };
                    MMA_BF16(acc[mt][nt], Af[mt], b2);
                }
            }
        }
    }

    // ---- epilogue in two 64-row halves (smem bounce, fused ops) ----
    constexpr int SSTR = BNT + 4;
    float* stile = (float*)smem;                 // [64][SSTR]
    const int groupID = lane >> 2, tig = lane & 3;
    constexpr int TPR = BNT / 4;                 // threads per row
    constexpr int RPI = NTHR / TPR;              // rows per iteration
    const int ecol = (tid % TPR) * 4;
    const int erow = tid / TPR;
    int col = n0 + ecol;

    float4 b4 = make_float4(0.f, 0.f, 0.f, 0.f), d4 = b4;
    if (HAS_BIAS) b4 = *(const float4*)(bias + col);
    if (HAS_DAUX) d4 = *(const float4*)(dvec + col);

    #pragma unroll
    for (int half = 0; half < 2; half++) {
        __syncthreads();
        if (wm == half) {
            #pragma unroll
            for (int mt = 0; mt < 4; mt++) {
                int r0 = mt * 16 + groupID;
                #pragma unroll
                for (int nt = 0; nt < NT; nt++) {
                    int c = wn * WN + nt * 8 + tig * 2;
                    *(float2*)&stile[r0 * SSTR + c]       = make_float2(acc[mt][nt][0], acc[mt][nt][1]);
                    *(float2*)&stile[(r0 + 8) * SSTR + c] = make_float2(acc[mt][nt][2], acc[mt][nt][3]);
                }
            }
        }
        __syncthreads();

        #pragma unroll
        for (int it = 0; it < 64 / RPI; it++) {
            int rl = it * RPI + erow;
            int row = m0 + half * 64 + rl;
            float4 v = *(float4*)&stile[rl * SSTR + ecol];
            if (HAS_BIAS) { v.x += b4.x; v.y += b4.y; v.z += b4.z; v.w += b4.w; }
            if (HAS_DAUX) {
                float4 a4 = *(const float4*)(aux + (size_t)row * Nc + col);
                v.x += d4.x * a4.x; v.y += d4.y * a4.y; v.z += d4.z * a4.z; v.w += d4.w * a4.w;
            }
            if (HAS_RES) {
                float4 r4 = *(const float4*)(res + (size_t)row * Nc + col);
                v.x += r4.x; v.y += r4.y; v.z += r4.z; v.w += r4.w;
            }
            if (WF32) *(float4*)(Cf + (size_t)row * Nc + col) = v;
            if (WSPLIT) {
                __nv_bfloat16 h0 = __float2bfloat16(v.x), h1 = __float2bfloat16(v.y);
                __nv_bfloat16 h2 = __float2bfloat16(v.z), h3 = __float2bfloat16(v.w);
                __nv_bfloat16 l0 = __float2bfloat16(v.x - __bfloat162float(h0));
                __nv_bfloat16 l1 = __float2bfloat16(v.y - __bfloat162float(h1));
                __nv_bfloat16 l2 = __float2bfloat16(v.z - __bfloat162float(h2));
                __nv_bfloat16 l3 = __float2bfloat16(v.w - __bfloat162float(h3));
                uint2 hv = make_uint2(pack_bf2(h0, h1), pack_bf2(h2, h3));
                uint2 lv = make_uint2(pack_bf2(l0, l1), pack_bf2(l2, l3));
                __nv_bfloat16* bp = Csp + (size_t)row * 2 * Nc + col;
                *(uint2*)(bp)      = hv;
                *(uint2*)(bp + Nc) = lv;
            }
        }
    }
}

// ---------------- chunked scan (== FFT causal conv) ----------------
#define CHUNK 64
#define NCHUNK (SEQ_LEN / CHUNK)

__global__ __launch_bounds__(128) void scan1(const float* __restrict__ proj,
                                             const float* __restrict__ A_log,
                                             float* __restrict__ carry)
{
    int c = blockIdx.x, b = blockIdx.y, s = threadIdx.x;
    float lam = expf(-expf(A_log[s]));
    size_t row0 = (size_t)b * SEQ_LEN + c * CHUNK;
    float y = 0.f;
    #pragma unroll 8
    for (int t = 0; t < CHUNK; t++) {
        const float* p = proj + (row0 + t) * NPROJ;
        y = fmaf(lam, y, p[s] * p[128 + s]);
    }
    carry[(b * NCHUNK + c) * D_STATE + s] = y;
}

__global__ __launch_bounds__(128) void scan2(const float* __restrict__ A_log,
                                             float* __restrict__ carry)
{
    int b = blockIdx.x, s = threadIdx.x;
    float lam64 = expf(-expf(A_log[s]) * (float)CHUNK);
    float S = 0.f;
    for (int c = 0; c < NCHUNK; c++) {
        size_t i = (size_t)(b * NCHUNK + c) * D_STATE + s;
        float f = carry[i];
        carry[i] = S;
        S = fmaf(lam64, S, f);
    }
}

__global__ __launch_bounds__(128) void scan3(const float* __restrict__ proj,
                                             const float* __restrict__ A_log,
                                             const float* __restrict__ carry,
                                             __nv_bfloat16* __restrict__ ysp)
{
    int c = blockIdx.x, b = blockIdx.y, s = threadIdx.x;
    float lam = expf(-expf(A_log[s]));
    float y = carry[(b * NCHUNK + c) * D_STATE + s];
    size_t row0 = (size_t)b * SEQ_LEN + c * CHUNK;
    #pragma unroll 4
    for (int t = 0; t < CHUNK; t++) {
        size_t row = row0 + t;
        const float* p = proj + row * NPROJ;
        y = fmaf(lam, y, p[s] * p[128 + s]);
        float o = y * p[256 + s];
        __nv_bfloat16 hi = __float2bfloat16(o);
        __nv_bfloat16 lo = __float2bfloat16(o - __bfloat162float(hi));
        __nv_bfloat16* bp = ysp + row * 2 * D_STATE;
        bp[s]           = hi;
        bp[D_STATE + s] = lo;
    }
}

// ---------------- launch ----------------
#define GSM256 (NSTAGE * (BM + 256) * RSB)   // 122880
#define GSM128 (NSTAGE * (BM + 128) * RSB)   // 81920

extern "C" void kernel_launch(void* const* d_in, const int* in_sizes, int n_in,
                              void* d_out, int out_size)
{
    const float* x        = (const float*)d_in[0];
    const float* ln_gamma = (const float*)d_in[1];
    const float* ln_beta  = (const float*)d_in[2];
    const float* W_in     = (const float*)d_in[3];
    const float* b_in     = (const float*)d_in[4];
    const float* W_xs     = (const float*)d_in[5];
    const float* W_B      = (const float*)d_in[6];
    const float* b_B      = (const float*)d_in[7];
    const float* W_C      = (const float*)d_in[8];
    const float* b_C      = (const float*)d_in[9];
    const float* A_log    = (const float*)d_in[10];
    const float* Dv       = (const float*)d_in[11];
    const float* W_so     = (const float*)d_in[12];
    const float* W_out    = (const float*)d_in[13];
    const float* b_out    = (const float*)d_in[14];
    float* out = (float*)d_out;

    __nv_bfloat16 *p_xn_sp, *p_z_sp, *p_ysc_sp, *p_y1_sp;
    __nv_bfloat16 *p_Win, *p_Wpk, *p_Wso, *p_Wout;
    float *p_z, *p_proj, *p_bpk, *p_carry;
    cudaGetSymbolAddress((void**)&p_xn_sp,  g_xn_sp);
    cudaGetSymbolAddress((void**)&p_z,      g_z);
    cudaGetSymbolAddress((void**)&p_z_sp,   g_z_sp);
    cudaGetSymbolAddress((void**)&p_proj,   g_proj);
    cudaGetSymbolAddress((void**)&p_ysc_sp, g_ysc_sp);
    cudaGetSymbolAddress((void**)&p_y1_sp,  g_y1_sp);
    cudaGetSymbolAddress((void**)&p_Win,    g_Win_p);
    cudaGetSymbolAddress((void**)&p_Wpk,    g_Wpk_p);
    cudaGetSymbolAddress((void**)&p_Wso,    g_Wso_p);
    cudaGetSymbolAddress((void**)&p_Wout,   g_Wout_p);
    cudaGetSymbolAddress((void**)&p_bpk,    g_bpk);
    cudaGetSymbolAddress((void**)&p_carry,  g_carry);

    cudaFuncSetAttribute(gemm_tc<256, true,  false, false, true,  true >, cudaFuncAttributeMaxDynamicSharedMemorySize, GSM256);
    cudaFuncSetAttribute(gemm_tc<128, true,  false, false, true,  false>, cudaFuncAttributeMaxDynamicSharedMemorySize, GSM128);
    cudaFuncSetAttribute(gemm_tc<256, false, true,  false, false, true >, cudaFuncAttributeMaxDynamicSharedMemorySize, GSM256);
    cudaFuncSetAttribute(gemm_tc<256, true,  false, true,  true,  false>, cudaFuncAttributeMaxDynamicSharedMemorySize, GSM256);

    // ---- weight prep ([hi|lo] physical) ----
    prep_weight<<<(D_MODEL * D_MODEL + 255) / 256, 256>>>(W_in,  p_Win,  D_MODEL, D_MODEL);
    prep_weight<<<(D_MODEL * D_STATE + 255) / 256, 256>>>(W_xs,  p_Wpk,                              D_MODEL, D_STATE);
    prep_weight<<<(D_MODEL * D_STATE + 255) / 256, 256>>>(W_B,   p_Wpk + (size_t)128 * 2 * D_MODEL,  D_MODEL, D_STATE);
    prep_weight<<<(D_MODEL * D_STATE + 255) / 256, 256>>>(W_C,   p_Wpk + (size_t)256 * 2 * D_MODEL,  D_MODEL, D_STATE);
    prep_weight<<<(D_STATE * D_MODEL + 255) / 256, 256>>>(W_so,  p_Wso,  D_STATE, D_MODEL);
    prep_weight<<<(D_MODEL * D_MODEL + 255) / 256, 256>>>(W_out, p_Wout, D_MODEL, D_MODEL);
    prep_bias<<<1, NPROJ>>>(b_B, b_C, p_bpk);

    // ---- 1. LayerNorm -> split bf16 ----
    ln_split_kernel<<<ROWS, 256>>>(x, ln_gamma, ln_beta, p_xn_sp);

    // ---- 2. z = xn @ W_in + b_in (fp32 z + split z') ----
    gemm_tc<256, true, false, false, true, true><<<dim3(D_MODEL / 256, ROWS / BM), NTHR, GSM256>>>(
        p_xn_sp, p_Win, 3 * D_MODEL, D_MODEL, p_z, p_z_sp, b_in, nullptr, nullptr, nullptr);

    // ---- 3. packed projections: [xs | B | C] ----
    gemm_tc<128, true, false, false, true, false><<<dim3(NPROJ / 128, ROWS / BM), NTHR, GSM128>>>(
        p_z_sp, p_Wpk, 3 * D_MODEL, NPROJ, p_proj, nullptr, p_bpk, nullptr, nullptr, nullptr);

    // ---- 4. chunked linear recurrence (== FFT causal conv) ----
    scan1<<<dim3(NCHUNK, BATCH), 128>>>(p_proj, A_log, p_carry);
    scan2<<<BATCH, 128>>>(A_log, p_carry);
    scan3<<<dim3(NCHUNK, BATCH), 128>>>(p_proj, A_log, p_carry, p_ysc_sp);

    // ---- 5. y1 = ysc @ W_so + D*z (split only) ----
    gemm_tc<256, false, true, false, false, true><<<dim3(D_MODEL / 256, ROWS / BM), NTHR, GSM256>>>(
        p_ysc_sp, p_Wso, 3 * D_STATE, D_MODEL, nullptr, p_y1_sp, nullptr, Dv, p_z, nullptr);

    // ---- 6. out = y1 @ W_out + b_out + x ----
    gemm_tc<256, true, false, true, true, false><<<dim3(D_MODEL / 256, ROWS / BM), NTHR, GSM256>>>(
        p_y1_sp, p_Wout, 3 * D_MODEL, D_MODEL, out, nullptr, b_out, nullptr, nullptr, x);
}

// round 6
// speedup vs baseline: 1.8313x; 1.7866x over previous
#include <cuda_runtime.h>
#include <cuda_fp16.h>
#include <math.h>
#include <stdint.h>

#define D_MODEL 1024
#define D_STATE 128
#define SEQ_LEN 4096
#define BATCH   4
#define ROWS    (BATCH * SEQ_LEN)        // 16384
#define LN_EPS  1e-3f
#define NPROJ   (3 * D_STATE)            // 384 (xs|B|C packed)

// ---------------- scratch (allocation-free: __device__ globals) ----------------
// activations: plain fp16 (stride K). weights: fp16 [hi | lo] (stride 2K).
__device__ __half g_xn_h [(size_t)ROWS * D_MODEL];
__device__ float  g_z    [(size_t)ROWS * D_MODEL];
__device__ __half g_z_h  [(size_t)ROWS * D_MODEL];
__device__ float  g_proj [(size_t)ROWS * NPROJ];
__device__ __half g_ysc_h[(size_t)ROWS * D_STATE];
__device__ __half g_y1_h [(size_t)ROWS * D_MODEL];
__device__ __half g_Win_p [(size_t)D_MODEL * 2 * D_MODEL];
__device__ __half g_Wpk_p [(size_t)NPROJ   * 2 * D_MODEL];
__device__ __half g_Wso_p [(size_t)D_MODEL * 2 * D_STATE];
__device__ __half g_Wout_p[(size_t)D_MODEL * 2 * D_MODEL];
__device__ float g_bpk[NPROJ];
__device__ float g_carry[BATCH * 64 * D_STATE];

// ---------------- helpers ----------------
__device__ __forceinline__ uint32_t cvta_smem(const void* p) {
    uint32_t a;
    asm("{ .reg .u64 t; cvta.to.shared.u64 t, %1; cvt.u32.u64 %0, t; }" : "=r"(a) : "l"(p));
    return a;
}
__device__ __forceinline__ uint32_t pack_h2(__half a, __half b) {
    __half2 t; t.x = a; t.y = b;
    return *reinterpret_cast<uint32_t*>(&t);
}

// ---------------- LayerNorm -> fp16 ----------------
__global__ __launch_bounds__(256) void ln_h_kernel(
    const float* __restrict__ x, const float* __restrict__ gamma,
    const float* __restrict__ beta, __half* __restrict__ outp)
{
    int row = blockIdx.x;
    int tid = threadIdx.x;
    const float4* xr = (const float4*)(x + (size_t)row * D_MODEL);
    float4 v = xr[tid];

    float s  = v.x + v.y + v.z + v.w;
    float sq = v.x*v.x + v.y*v.y + v.z*v.z + v.w*v.w;
    #pragma unroll
    for (int o = 16; o > 0; o >>= 1) {
        s  += __shfl_xor_sync(0xffffffffu, s,  o);
        sq += __shfl_xor_sync(0xffffffffu, sq, o);
    }
    __shared__ float sh_s[8], sh_q[8];
    int wid = tid >> 5, lid = tid & 31;
    if (lid == 0) { sh_s[wid] = s; sh_q[wid] = sq; }
    __syncthreads();
    if (wid == 0) {
        float a = (lid < 8) ? sh_s[lid] : 0.f;
        float b = (lid < 8) ? sh_q[lid] : 0.f;
        #pragma unroll
        for (int o = 4; o > 0; o >>= 1) {
            a += __shfl_xor_sync(0xffffffffu, a, o);
            b += __shfl_xor_sync(0xffffffffu, b, o);
        }
        if (lid == 0) { sh_s[0] = a; sh_q[0] = b; }
    }
    __syncthreads();
    float mu   = sh_s[0] * (1.0f / D_MODEL);
    float var  = sh_q[0] * (1.0f / D_MODEL) - mu * mu;
    float rstd = rsqrtf(var + LN_EPS);

    float4 gv = ((const float4*)gamma)[tid];
    float4 bv = ((const float4*)beta)[tid];
    float o0 = (v.x - mu) * rstd * gv.x + bv.x;
    float o1 = (v.y - mu) * rstd * gv.y + bv.y;
    float o2 = (v.z - mu) * rstd * gv.z + bv.z;
    float o3 = (v.w - mu) * rstd * gv.w + bv.w;

    uint2 hv = make_uint2(pack_h2(__float2half_rn(o0), __float2half_rn(o1)),
                          pack_h2(__float2half_rn(o2), __float2half_rn(o3)));
    *(uint2*)(outp + (size_t)row * D_MODEL + tid * 4) = hv;
}

// ---------------- weight prep: W[K,N] fp32 -> Wp[N][2K] fp16 [hi | lo] ----------------
__global__ void prep_weight(const float* __restrict__ W, __half* __restrict__ Wp,
                            int K, int N)
{
    int idx = blockIdx.x * blockDim.x + threadIdx.x;
    if (idx >= K * N) return;
    int k = idx / N, n = idx % N;
    float w = W[idx];
    __half hi = __float2half_rn(w);
    __half lo = __float2half_rn(w - __half2float(hi));
    size_t base = (size_t)n * 2 * K;
    Wp[base + k]     = hi;
    Wp[base + K + k] = lo;
}

__global__ void prep_bias(const float* __restrict__ bB, const float* __restrict__ bC,
                          float* __restrict__ bp)
{
    int i = threadIdx.x;
    bp[i] = (i < 128) ? 0.f : ((i < 256) ? bB[i - 128] : bC[i - 256]);
}

// ---------------- HMMA GEMM: C[M,Nc] = A_fp16[M,K] @ (W_hi + W_lo)[Nc,K]^T ----------------
// Per physical K-chunk: one A tile + B_hi + B_lo tiles, both products into same acc.
// CTA 128x128, 8 warps (2M x 4N), warp tile 64x32, BK=32, 3-stage cp.async, 2 CTAs/SM.
#define BM 128
#define BN 128
#define BK 32
#define NSTAGE 3
#define RSB 80                                   // smem row stride bytes (40 fp16)
#define TILE_B (BM * RSB)                        // 10240 per operand tile
#define STAGE  (3 * TILE_B)                      // 30720 (A | Bhi | Blo)
#define GSM    (NSTAGE * STAGE)                  // 92160

#define MMA_F16(d, a, b) \
    asm volatile( \
        "mma.sync.aligned.m16n8k16.row.col.f32.f16.f16.f32 " \
        "{%0,%1,%2,%3}, {%4,%5,%6,%7}, {%8,%9}, {%0,%1,%2,%3};" \
        : "+f"((d)[0]), "+f"((d)[1]), "+f"((d)[2]), "+f"((d)[3]) \
        : "r"((a)[0]), "r"((a)[1]), "r"((a)[2]), "r"((a)[3]), \
          "r"((b)[0]), "r"((b)[1]))

#define LDSM_X4(r, addr) \
    asm volatile("ldmatrix.sync.aligned.m8n8.x4.shared.b16 {%0,%1,%2,%3}, [%4];" \
        : "=r"((r)[0]), "=r"((r)[1]), "=r"((r)[2]), "=r"((r)[3]) : "r"(addr))

template<bool HAS_BIAS, bool HAS_DAUX, bool HAS_RES, bool WF32, bool WH16>
__global__ __launch_bounds__(256, 2)
void gemm_tc(const __half* __restrict__ A, const __half* __restrict__ Bw,
             int K, int Nc,
             float* __restrict__ Cf, __half* __restrict__ Ch,
             const float* __restrict__ bias, const float* __restrict__ dvec,
             const float* __restrict__ aux, const float* __restrict__ res)
{
    extern __shared__ __align__(128) char smem[];
    const int tid  = threadIdx.x;
    const int warp = tid >> 5, lane = tid & 31;
    const int wm = warp & 1, wn = warp >> 1;     // 2 x 4 warp grid
    const int m0 = blockIdx.y * BM, n0 = blockIdx.x * BN;
    const uint32_t smem_base = cvta_smem(smem);

    const int NKP = K / BK;                      // physical chunks
    const size_t arow_bytes = (size_t)K * 2;     // A: plain fp16
    const size_t brow_bytes = (size_t)K * 4;     // B: [hi|lo]
    const __half* Ab = A  + (size_t)m0 * K;
    const __half* Bb = Bw + (size_t)n0 * 2 * K;

    float acc[4][4][4];
    #pragma unroll
    for (int i = 0; i < 4; i++)
        #pragma unroll
        for (int j = 0; j < 4; j++)
            #pragma unroll
            for (int e = 0; e < 4; e++) acc[i][j][e] = 0.f;

    auto load_stage = [&](int sk, int buf) {
        const uint32_t sb = smem_base + buf * STAGE;
        const size_t kb = (size_t)sk * 64;       // 64 bytes = 32 fp16 per chunk
        #pragma unroll
        for (int j = 0; j < 2; j++) {
            int chunk = tid + j * 256;
            int row = chunk >> 2, cb = chunk & 3;
            const char* ga = (const char*)Ab + (size_t)row * arow_bytes + kb + cb * 16;
            asm volatile("cp.async.cg.shared.global [%0], [%1], 16;"
                         :: "r"(sb + row * RSB + cb * 16), "l"(ga));
        }
        #pragma unroll
        for (int j = 0; j < 2; j++) {
            int chunk = tid + j * 256;
            int row = chunk >> 2, cb = chunk & 3;
            const char* gh = (const char*)Bb + (size_t)row * brow_bytes + kb + cb * 16;
            asm volatile("cp.async.cg.shared.global [%0], [%1], 16;"
                         :: "r"(sb + TILE_B + row * RSB + cb * 16), "l"(gh));
        }
        #pragma unroll
        for (int j = 0; j < 2; j++) {
            int chunk = tid + j * 256;
            int row = chunk >> 2, cb = chunk & 3;
            const char* gl = (const char*)Bb + (size_t)row * brow_bytes + (size_t)K * 2 + kb + cb * 16;
            asm volatile("cp.async.cg.shared.global [%0], [%1], 16;"
                         :: "r"(sb + 2 * TILE_B + row * RSB + cb * 16), "l"(gl));
        }
        asm volatile("cp.async.commit_group;");
    };

    #pragma unroll
    for (int s = 0; s < NSTAGE - 1; s++) load_stage(s, s);

    const uint32_t lrow = (lane & 15);
    const uint32_t lkb  = (lane >> 4) * 16;

    for (int i = 0; i < NKP; i++) {
        asm volatile("cp.async.wait_group 1;");
        __syncthreads();

        int nxt = i + NSTAGE - 1;
        if (nxt < NKP) load_stage(nxt, nxt % NSTAGE);
        else           asm volatile("cp.async.commit_group;");

        const uint32_t sb = smem_base + (i % NSTAGE) * STAGE;
        const uint32_t abase  = sb + (wm * 64) * RSB;
        const uint32_t bhbase = sb + TILE_B     + (wn * 32) * RSB;
        const uint32_t blbase = sb + 2 * TILE_B + (wn * 32) * RSB;

        #pragma unroll
        for (int ks = 0; ks < 2; ks++) {
            uint32_t Af[4][4], Bh[2][4], Bl[2][4];
            #pragma unroll
            for (int mt = 0; mt < 4; mt++)
                LDSM_X4(Af[mt], abase + (mt * 16 + lrow) * RSB + ks * 32 + lkb);
            #pragma unroll
            for (int g = 0; g < 2; g++)
                LDSM_X4(Bh[g], bhbase + (g * 16 + lrow) * RSB + ks * 32 + lkb);
            #pragma unroll
            for (int g = 0; g < 2; g++)
                LDSM_X4(Bl[g], blbase + (g * 16 + lrow) * RSB + ks * 32 + lkb);

            #pragma unroll
            for (int mt = 0; mt < 4; mt++) {
                #pragma unroll
                for (int nt = 0; nt < 4; nt++) {
                    uint32_t bh2[2] = { Bh[nt >> 1][nt & 1], Bh[nt >> 1][(nt & 1) + 2] };
                    MMA_F16(acc[mt][nt], Af[mt], bh2);
                }
            }
            #pragma unroll
            for (int mt = 0; mt < 4; mt++) {
                #pragma unroll
                for (int nt = 0; nt < 4; nt++) {
                    uint32_t bl2[2] = { Bl[nt >> 1][nt & 1], Bl[nt >> 1][(nt & 1) + 2] };
                    MMA_F16(acc[mt][nt], Af[mt], bl2);
                }
            }
        }
    }
    __syncthreads();   // all LDSM done before smem reuse

    // ---- acc -> smem bounce ----
    float* stile = (float*)smem;               // [128][132]
    const int groupID = lane >> 2, tig = lane & 3;
    #pragma unroll
    for (int mt = 0; mt < 4; mt++) {
        int r0 = wm * 64 + mt * 16 + groupID;
        #pragma unroll
        for (int nt = 0; nt < 4; nt++) {
            int c = wn * 32 + nt * 8 + tig * 2;
            *(float2*)&stile[r0 * 132 + c]       = make_float2(acc[mt][nt][0], acc[mt][nt][1]);
            *(float2*)&stile[(r0 + 8) * 132 + c] = make_float2(acc[mt][nt][2], acc[mt][nt][3]);
        }
    }
    __syncthreads();

    // ---- fused coalesced epilogue: warp w covers rows w*16 .. w*16+15 ----
    float4 b4 = make_float4(0.f, 0.f, 0.f, 0.f), d4 = b4;
    int col = n0 + lane * 4;
    if (HAS_BIAS) b4 = *(const float4*)(bias + col);
    if (HAS_DAUX) d4 = *(const float4*)(dvec + col);

    #pragma unroll 4
    for (int rr = 0; rr < 16; rr++) {
        int r = warp * 16 + rr;
        int row = m0 + r;
        float4 v = *(float4*)&stile[r * 132 + lane * 4];
        if (HAS_BIAS) { v.x += b4.x; v.y += b4.y; v.z += b4.z; v.w += b4.w; }
        if (HAS_DAUX) {
            float4 a4 = *(const float4*)(aux + (size_t)row * Nc + col);
            v.x += d4.x * a4.x; v.y += d4.y * a4.y; v.z += d4.z * a4.z; v.w += d4.w * a4.w;
        }
        if (HAS_RES) {
            float4 r4 = *(const float4*)(res + (size_t)row * Nc + col);
            v.x += r4.x; v.y += r4.y; v.z += r4.z; v.w += r4.w;
        }
        if (WF32) *(float4*)(Cf + (size_t)row * Nc + col) = v;
        if (WH16) {
            uint2 hv = make_uint2(pack_h2(__float2half_rn(v.x), __float2half_rn(v.y)),
                                  pack_h2(__float2half_rn(v.z), __float2half_rn(v.w)));
            *(uint2*)(Ch + (size_t)row * Nc + col) = hv;
        }
    }
}

// ---------------- chunked scan (== FFT causal conv) ----------------
#define CHUNK 64
#define NCHUNK (SEQ_LEN / CHUNK)

__global__ __launch_bounds__(128) void scan1(const float* __restrict__ proj,
                                             const float* __restrict__ A_log,
                                             float* __restrict__ carry)
{
    int c = blockIdx.x, b = blockIdx.y, s = threadIdx.x;
    float lam = expf(-expf(A_log[s]));
    size_t row0 = (size_t)b * SEQ_LEN + c * CHUNK;
    float y = 0.f;
    #pragma unroll 8
    for (int t = 0; t < CHUNK; t++) {
        const float* p = proj + (row0 + t) * NPROJ;
        y = fmaf(lam, y, p[s] * p[128 + s]);
    }
    carry[(b * NCHUNK + c) * D_STATE + s] = y;
}

__global__ __launch_bounds__(128) void scan2(const float* __restrict__ A_log,
                                             float* __restrict__ carry)
{
    int b = blockIdx.x, s = threadIdx.x;
    float lam64 = expf(-expf(A_log[s]) * (float)CHUNK);
    float S = 0.f;
    for (int c = 0; c < NCHUNK; c++) {
        size_t i = (size_t)(b * NCHUNK + c) * D_STATE + s;
        float f = carry[i];
        carry[i] = S;
        S = fmaf(lam64, S, f);
    }
}

__global__ __launch_bounds__(128) void scan3(const float* __restrict__ proj,
                                             const float* __restrict__ A_log,
                                             const float* __restrict__ carry,
                                             __half* __restrict__ ysh)
{
    int c = blockIdx.x, b = blockIdx.y, s = threadIdx.x;
    float lam = expf(-expf(A_log[s]));
    float y = carry[(b * NCHUNK + c) * D_STATE + s];
    size_t row0 = (size_t)b * SEQ_LEN + c * CHUNK;
    #pragma unroll 4
    for (int t = 0; t < CHUNK; t++) {
        size_t row = row0 + t;
        const float* p = proj + row * NPROJ;
        y = fmaf(lam, y, p[s] * p[128 + s]);
        ysh[row * D_STATE + s] = __float2half_rn(y * p[256 + s]);
    }
}

// ---------------- launch ----------------
extern "C" void kernel_launch(void* const* d_in, const int* in_sizes, int n_in,
                              void* d_out, int out_size)
{
    const float* x        = (const float*)d_in[0];
    const float* ln_gamma = (const float*)d_in[1];
    const float* ln_beta  = (const float*)d_in[2];
    const float* W_in     = (const float*)d_in[3];
    const float* b_in     = (const float*)d_in[4];
    const float* W_xs     = (const float*)d_in[5];
    const float* W_B      = (const float*)d_in[6];
    const float* b_B      = (const float*)d_in[7];
    const float* W_C      = (const float*)d_in[8];
    const float* b_C      = (const float*)d_in[9];
    const float* A_log    = (const float*)d_in[10];
    const float* Dv       = (const float*)d_in[11];
    const float* W_so     = (const float*)d_in[12];
    const float* W_out    = (const float*)d_in[13];
    const float* b_out    = (const float*)d_in[14];
    float* out = (float*)d_out;

    __half *p_xn_h, *p_z_h, *p_ysc_h, *p_y1_h;
    __half *p_Win, *p_Wpk, *p_Wso, *p_Wout;
    float *p_z, *p_proj, *p_bpk, *p_carry;
    cudaGetSymbolAddress((void**)&p_xn_h,  g_xn_h);
    cudaGetSymbolAddress((void**)&p_z,     g_z);
    cudaGetSymbolAddress((void**)&p_z_h,   g_z_h);
    cudaGetSymbolAddress((void**)&p_proj,  g_proj);
    cudaGetSymbolAddress((void**)&p_ysc_h, g_ysc_h);
    cudaGetSymbolAddress((void**)&p_y1_h,  g_y1_h);
    cudaGetSymbolAddress((void**)&p_Win,   g_Win_p);
    cudaGetSymbolAddress((void**)&p_Wpk,   g_Wpk_p);
    cudaGetSymbolAddress((void**)&p_Wso,   g_Wso_p);
    cudaGetSymbolAddress((void**)&p_Wout,  g_Wout_p);
    cudaGetSymbolAddress((void**)&p_bpk,   g_bpk);
    cudaGetSymbolAddress((void**)&p_carry, g_carry);

    cudaFuncSetAttribute(gemm_tc<true,  false, false, true,  true >, cudaFuncAttributeMaxDynamicSharedMemorySize, GSM);
    cudaFuncSetAttribute(gemm_tc<true,  false, false, true,  false>, cudaFuncAttributeMaxDynamicSharedMemorySize, GSM);
    cudaFuncSetAttribute(gemm_tc<false, true,  false, false, true >, cudaFuncAttributeMaxDynamicSharedMemorySize, GSM);
    cudaFuncSetAttribute(gemm_tc<true,  false, true,  true,  false>, cudaFuncAttributeMaxDynamicSharedMemorySize, GSM);

    // ---- weight prep ([hi|lo] fp16) ----
    prep_weight<<<(D_MODEL * D_MODEL + 255) / 256, 256>>>(W_in,  p_Win,  D_MODEL, D_MODEL);
    prep_weight<<<(D_MODEL * D_STATE + 255) / 256, 256>>>(W_xs,  p_Wpk,                              D_MODEL, D_STATE);
    prep_weight<<<(D_MODEL * D_STATE + 255) / 256, 256>>>(W_B,   p_Wpk + (size_t)128 * 2 * D_MODEL,  D_MODEL, D_STATE);
    prep_weight<<<(D_MODEL * D_STATE + 255) / 256, 256>>>(W_C,   p_Wpk + (size_t)256 * 2 * D_MODEL,  D_MODEL, D_STATE);
    prep_weight<<<(D_STATE * D_MODEL + 255) / 256, 256>>>(W_so,  p_Wso,  D_STATE, D_MODEL);
    prep_weight<<<(D_MODEL * D_MODEL + 255) / 256, 256>>>(W_out, p_Wout, D_MODEL, D_MODEL);
    prep_bias<<<1, NPROJ>>>(b_B, b_C, p_bpk);

    // ---- 1. LayerNorm -> fp16 ----
    ln_h_kernel<<<ROWS, 256>>>(x, ln_gamma, ln_beta, p_xn_h);

    // ---- 2. z = xn @ W_in + b_in (fp32 z + fp16 z) ----
    gemm_tc<true, false, false, true, true><<<dim3(D_MODEL / BN, ROWS / BM), 256, GSM>>>(
        p_xn_h, p_Win, D_MODEL, D_MODEL, p_z, p_z_h, b_in, nullptr, nullptr, nullptr);

    // ---- 3. packed projections: [xs | B | C] ----
    gemm_tc<true, false, false, true, false><<<dim3(NPROJ / BN, ROWS / BM), 256, GSM>>>(
        p_z_h, p_Wpk, D_MODEL, NPROJ, p_proj, nullptr, p_bpk, nullptr, nullptr, nullptr);

    // ---- 4. chunked linear recurrence (== FFT causal conv) ----
    scan1<<<dim3(NCHUNK, BATCH), 128>>>(p_proj, A_log, p_carry);
    scan2<<<BATCH, 128>>>(A_log, p_carry);
    scan3<<<dim3(NCHUNK, BATCH), 128>>>(p_proj, A_log, p_carry, p_ysc_h);

    // ---- 5. y1 = ysc @ W_so + D*z (fp16 only) ----
    gemm_tc<false, true, false, false, true><<<dim3(D_MODEL / BN, ROWS / BM), 256, GSM>>>(
        p_ysc_h, p_Wso, D_STATE, D_MODEL, nullptr, p_y1_h, nullptr, Dv, p_z, nullptr);

    // ---- 6. out = y1 @ W_out + b_out + x ----
    gemm_tc<true, false, true, true, false><<<dim3(D_MODEL / BN, ROWS / BM), 256, GSM>>>(
        p_y1_h, p_Wout, D_MODEL, D_MODEL, out, nullptr, b_out, nullptr, nullptr, x);
}

// round 8
// speedup vs baseline: 1.8807x; 1.0270x over previous
#include <cuda_runtime.h>
#include <cuda_fp16.h>
#include <math.h>
#include <stdint.h>

#define D_MODEL 1024
#define D_STATE 128
#define SEQ_LEN 4096
#define BATCH   4
#define ROWS    (BATCH * SEQ_LEN)        // 16384
#define LN_EPS  1e-3f
#define NPROJ   384                      // xs|B|C packed
#define ACTW    1152                     // [xn(1024) | ysc(128)]
#define KOUT    1152

// ---------------- scratch (allocation-free: __device__ globals) ----------------
__device__ __half g_act [(size_t)ROWS * ACTW];             // 36 MB
__device__ float  g_proj[(size_t)ROWS * NPROJ];            // 24 MB
// A-side splits [M][2K] fp16 [hi|lo]
__device__ __half g_WinA[(size_t)D_MODEL * 2 * D_MODEL];
__device__ __half g_WsoA[(size_t)D_STATE * 2 * D_MODEL];
// B-side splits [N][2K] (transposed)
__device__ __half g_WpB  [(size_t)NPROJ   * 2 * D_MODEL];
__device__ __half g_WdB  [(size_t)D_MODEL * 2 * D_MODEL];
__device__ __half g_WoutB[(size_t)D_MODEL * 2 * D_MODEL];
// combined big-GEMM weights
__device__ __half g_W4  [(size_t)NPROJ   * 2 * D_MODEL];   // [384][2048], Kb=1024
__device__ __half g_Wcat[(size_t)D_MODEL * 2 * KOUT];      // [1024][2304], Kb=1152
__device__ float g_b4[NPROJ];
__device__ float g_b5[D_MODEL];
__device__ float g_carry[BATCH * 64 * D_STATE];

// ---------------- helpers ----------------
__device__ __forceinline__ uint32_t cvta_smem(const void* p) {
    uint32_t a;
    asm("{ .reg .u64 t; cvta.to.shared.u64 t, %1; cvt.u32.u64 %0, t; }" : "=r"(a) : "l"(p));
    return a;
}
__device__ __forceinline__ uint32_t pack_h2(__half a, __half b) {
    __half2 t; t.x = a; t.y = b;
    return *reinterpret_cast<uint32_t*>(&t);
}

#define MMA_F16(d, a, b) \
    asm volatile( \
        "mma.sync.aligned.m16n8k16.row.col.f32.f16.f16.f32 " \
        "{%0,%1,%2,%3}, {%4,%5,%6,%7}, {%8,%9}, {%0,%1,%2,%3};" \
        : "+f"((d)[0]), "+f"((d)[1]), "+f"((d)[2]), "+f"((d)[3]) \
        : "r"((a)[0]), "r"((a)[1]), "r"((a)[2]), "r"((a)[3]), \
          "r"((b)[0]), "r"((b)[1]))

#define LDSM_X4(r, addr) \
    asm volatile("ldmatrix.sync.aligned.m8n8.x4.shared.b16 {%0,%1,%2,%3}, [%4];" \
        : "=r"((r)[0]), "=r"((r)[1]), "=r"((r)[2]), "=r"((r)[3]) : "r"(addr))

// ---------------- LayerNorm -> fp16 into g_act (stride ACTW) ----------------
__global__ __launch_bounds__(256) void ln_h_kernel(
    const float* __restrict__ x, const float* __restrict__ gamma,
    const float* __restrict__ beta, __half* __restrict__ act)
{
    int row = blockIdx.x;
    int tid = threadIdx.x;
    const float4* xr = (const float4*)(x + (size_t)row * D_MODEL);
    float4 v = xr[tid];

    float s  = v.x + v.y + v.z + v.w;
    float sq = v.x*v.x + v.y*v.y + v.z*v.z + v.w*v.w;
    #pragma unroll
    for (int o = 16; o > 0; o >>= 1) {
        s  += __shfl_xor_sync(0xffffffffu, s,  o);
        sq += __shfl_xor_sync(0xffffffffu, sq, o);
    }
    __shared__ float sh_s[8], sh_q[8];
    int wid = tid >> 5, lid = tid & 31;
    if (lid == 0) { sh_s[wid] = s; sh_q[wid] = sq; }
    __syncthreads();
    if (wid == 0) {
        float a = (lid < 8) ? sh_s[lid] : 0.f;
        float b = (lid < 8) ? sh_q[lid] : 0.f;
        #pragma unroll
        for (int o = 4; o > 0; o >>= 1) {
            a += __shfl_xor_sync(0xffffffffu, a, o);
            b += __shfl_xor_sync(0xffffffffu, b, o);
        }
        if (lid == 0) { sh_s[0] = a; sh_q[0] = b; }
    }
    __syncthreads();
    float mu   = sh_s[0] * (1.0f / D_MODEL);
    float var  = sh_q[0] * (1.0f / D_MODEL) - mu * mu;
    float rstd = rsqrtf(var + LN_EPS);

    float4 gv = ((const float4*)gamma)[tid];
    float4 bv = ((const float4*)beta)[tid];
    float o0 = (v.x - mu) * rstd * gv.x + bv.x;
    float o1 = (v.y - mu) * rstd * gv.y + bv.y;
    float o2 = (v.z - mu) * rstd * gv.z + bv.z;
    float o3 = (v.w - mu) * rstd * gv.w + bv.w;

    uint2 hv = make_uint2(pack_h2(__float2half_rn(o0), __float2half_rn(o1)),
                          pack_h2(__float2half_rn(o2), __float2half_rn(o3)));
    *(uint2*)(act + (size_t)row * ACTW + tid * 4) = hv;
}

// ---------------- prep: A-side split X[M,K] -> [M][2K] [hi|lo] ----------------
__global__ void prep_split_A(const float* __restrict__ X, __half* __restrict__ XA,
                             int M, int K)
{
    int idx = blockIdx.x * blockDim.x + threadIdx.x;
    if (idx >= M * K) return;
    int m = idx / K, k = idx % K;
    float w = X[idx];
    __half hi = __float2half_rn(w);
    __half lo = __float2half_rn(w - __half2float(hi));
    size_t base = (size_t)m * 2 * K;
    XA[base + k]     = hi;
    XA[base + K + k] = lo;
}

// ---------------- prep: B-side split W[K,N] -> WB[n][2K] (transposed), opt row scale ----------------
__global__ void prep_split_B(const float* __restrict__ W, __half* __restrict__ WB,
                             int K, int N, const float* __restrict__ scale)
{
    int idx = blockIdx.x * blockDim.x + threadIdx.x;
    if (idx >= K * N) return;
    int k = idx / N, n = idx % N;
    float w = W[idx];
    if (scale) w *= scale[k];
    __half hi = __float2half_rn(w);
    __half lo = __float2half_rn(w - __half2float(hi));
    size_t base = (size_t)n * 2 * K;
    WB[base + k]     = hi;
    WB[base + K + k] = lo;
}

// ---------------- bias precompute ----------------
__global__ void bias4_k(const float* __restrict__ b_in,
                        const float* __restrict__ W_xs, const float* __restrict__ W_B,
                        const float* __restrict__ bB,  const float* __restrict__ W_C,
                        const float* __restrict__ bC,  float* __restrict__ b4)
{
    int n = blockIdx.x * 128 + threadIdx.x;          // grid 3 x 128
    float acc = 0.f;
    if (n < 128) {
        for (int j = 0; j < D_MODEL; j++) acc += b_in[j] * W_xs[j * 128 + n];
        b4[n] = acc;
    } else if (n < 256) {
        int c = n - 128;
        for (int j = 0; j < D_MODEL; j++) acc += b_in[j] * W_B[j * 128 + c];
        b4[n] = acc + bB[c];
    } else {
        int c = n - 256;
        for (int j = 0; j < D_MODEL; j++) acc += b_in[j] * W_C[j * 128 + c];
        b4[n] = acc + bC[c];
    }
}

__global__ void bias5_k(const float* __restrict__ b_in, const float* __restrict__ D,
                        const float* __restrict__ W_out, const float* __restrict__ b_out,
                        float* __restrict__ b5)
{
    int n = blockIdx.x * 256 + threadIdx.x;          // grid 4 x 256
    float acc = 0.f;
    for (int j = 0; j < D_MODEL; j++) acc += b_in[j] * D[j] * W_out[j * D_MODEL + n];
    b5[n] = acc + b_out[n];
}

// ---------------- precompute GEMM (3-term dual split, high precision) ----------------
// C[M,N] = A@B^T with A,B physical [·][2K] [hi|lo]; logical chunks A:[hi|lo|hi], B:[hi|hi|lo].
// Tile 128 x 64, 8 warps (2M x 4N), warp 64x16. Epilogue: transposed split scatter into
// Wbig[n][2*Kb] at column offset colOff.
#define PBM 128
#define PBN 64
#define PRSB 80
#define PTILEA (PBM * PRSB)                  // 10240
#define PSTAGE ((PBM + PBN) * PRSB)          // 15360
#define PGSM (3 * PSTAGE)                    // 46080

__global__ __launch_bounds__(256, 2)
void pgemm(const __half* __restrict__ A, const __half* __restrict__ B, int K,
           __half* __restrict__ Wbig, int Kb, int colOff)
{
    extern __shared__ __align__(128) char smem[];
    const int tid  = threadIdx.x;
    const int warp = tid >> 5, lane = tid & 31;
    const int wm = warp & 1, wn = warp >> 1;
    const int m0 = blockIdx.y * PBM, n0 = blockIdx.x * PBN;
    const uint32_t smem_base = cvta_smem(smem);

    const int KB = K / 32;
    const int NK = 3 * KB;
    const size_t row_bytes = (size_t)K * 4;          // 2K fp16
    const __half* Ab = A + (size_t)m0 * 2 * K;
    const __half* Bb = B + (size_t)n0 * 2 * K;

    float acc[4][2][4];
    #pragma unroll
    for (int i = 0; i < 4; i++)
        #pragma unroll
        for (int j = 0; j < 2; j++)
            #pragma unroll
            for (int e = 0; e < 4; e++) acc[i][j][e] = 0.f;

    auto load_stage = [&](int sk, int buf) {
        const uint32_t sb = smem_base + buf * PSTAGE;
        int lkA = (sk < 2 * KB) ? sk : sk - 2 * KB;   // [hi|lo|hi]
        int lkB = (sk < KB)     ? sk : sk - KB;       // [hi|hi|lo]
        const size_t kbA = (size_t)lkA * 64;
        const size_t kbB = (size_t)lkB * 64;
        #pragma unroll
        for (int j = 0; j < 2; j++) {
            int chunk = tid + j * 256;                // 512 A chunks
            int row = chunk >> 2, cb = chunk & 3;
            const char* ga = (const char*)Ab + (size_t)row * row_bytes + kbA + cb * 16;
            asm volatile("cp.async.cg.shared.global [%0], [%1], 16;"
                         :: "r"(sb + row * PRSB + cb * 16), "l"(ga));
        }
        {
            int chunk = tid;                          // 256 B chunks
            int row = chunk >> 2, cb = chunk & 3;
            const char* gb = (const char*)Bb + (size_t)row * row_bytes + kbB + cb * 16;
            asm volatile("cp.async.cg.shared.global [%0], [%1], 16;"
                         :: "r"(sb + PTILEA + row * PRSB + cb * 16), "l"(gb));
        }
        asm volatile("cp.async.commit_group;");
    };

    #pragma unroll
    for (int s = 0; s < 2; s++) load_stage(s, s);

    const uint32_t lrow = (lane & 15);
    const uint32_t lkb  = (lane >> 4) * 16;

    for (int i = 0; i < NK; i++) {
        asm volatile("cp.async.wait_group 1;");
        __syncthreads();
        int nxt = i + 2;
        if (nxt < NK) load_stage(nxt, nxt % 3);
        else          asm volatile("cp.async.commit_group;");

        const uint32_t sb = smem_base + (i % 3) * PSTAGE;
        const uint32_t abase = sb + (wm * 64) * PRSB;
        const uint32_t bbase = sb + PTILEA + (wn * 16) * PRSB;

        #pragma unroll
        for (int ks = 0; ks < 2; ks++) {
            uint32_t Af[4][4], Bf[4];
            #pragma unroll
            for (int mt = 0; mt < 4; mt++)
                LDSM_X4(Af[mt], abase + (mt * 16 + lrow) * PRSB + ks * 32 + lkb);
            LDSM_X4(Bf, bbase + lrow * PRSB + ks * 32 + lkb);

            #pragma unroll
            for (int mt = 0; mt < 4; mt++) {
                #pragma unroll
                for (int nt = 0; nt < 2; nt++) {
                    uint32_t b2[2] = { Bf[nt], Bf[nt + 2] };
                    MMA_F16(acc[mt][nt], Af[mt], b2);
                }
            }
        }
    }

    // transposed split scatter: Wbig[n][colOff + k] = hi, [Kb + colOff + k] = lo
    const int groupID = lane >> 2, tig = lane & 3;
    #pragma unroll
    for (int mt = 0; mt < 4; mt++) {
        #pragma unroll
        for (int nt = 0; nt < 2; nt++) {
            int r0 = m0 + wm * 64 + mt * 16 + groupID;
            int c0 = n0 + wn * 16 + nt * 8 + tig * 2;
            #pragma unroll
            for (int e = 0; e < 4; e++) {
                int r = r0 + (e >> 1) * 8;
                int c = c0 + (e & 1);
                float v = acc[mt][nt][e];
                __half hi = __float2half_rn(v);
                __half lo = __float2half_rn(v - __half2float(hi));
                size_t base = (size_t)c * 2 * Kb + colOff + r;
                Wbig[base]      = hi;
                Wbig[base + Kb] = lo;
            }
        }
    }
}

// ---------------- big GEMM: C[M,Nc] = A_fp16[M,K](lda) @ (W_hi+W_lo)[Nc,2K]^T ----------------
// CTA 128x128, 8 warps (2M x 4N), warp 64x32, BK=32, 3-stage, 2 CTAs/SM.
#define BM 128
#define BN 128
#define RSB 80
#define TILE_B (BM * RSB)                        // 10240
#define STAGE  (3 * TILE_B)                      // 30720 (A | Bhi | Blo)
#define GSM    (3 * STAGE)                       // 92160

template<bool HAS_BIAS, bool HAS_RES>
__global__ __launch_bounds__(256, 2)
void bgemm(const __half* __restrict__ A, int lda, const __half* __restrict__ Bw,
           int K, int Nc, float* __restrict__ Cf,
           const float* __restrict__ bias, const float* __restrict__ res)
{
    extern __shared__ __align__(128) char smem[];
    const int tid  = threadIdx.x;
    const int warp = tid >> 5, lane = tid & 31;
    const int wm = warp & 1, wn = warp >> 1;
    const int m0 = blockIdx.y * BM, n0 = blockIdx.x * BN;
    const uint32_t smem_base = cvta_smem(smem);

    const int NKP = K / 32;
    const size_t arow_bytes = (size_t)lda * 2;
    const size_t brow_bytes = (size_t)K * 4;
    const size_t lo_off     = (size_t)K * 2;
    const __half* Ab = A  + (size_t)m0 * lda;
    const __half* Bb = Bw + (size_t)n0 * 2 * K;

    float acc[4][4][4];
    #pragma unroll
    for (int i = 0; i < 4; i++)
        #pragma unroll
        for (int j = 0; j < 4; j++)
            #pragma unroll
            for (int e = 0; e < 4; e++) acc[i][j][e] = 0.f;

    auto load_stage = [&](int sk, int buf) {
        const uint32_t sb = smem_base + buf * STAGE;
        const size_t kb = (size_t)sk * 64;
        #pragma unroll
        for (int j = 0; j < 2; j++) {
            int chunk = tid + j * 256;
            int row = chunk >> 2, cb = chunk & 3;
            const char* ga = (const char*)Ab + (size_t)row * arow_bytes + kb + cb * 16;
            asm volatile("cp.async.cg.shared.global [%0], [%1], 16;"
                         :: "r"(sb + row * RSB + cb * 16), "l"(ga));
        }
        #pragma unroll
        for (int j = 0; j < 2; j++) {
            int chunk = tid + j * 256;
            int row = chunk >> 2, cb = chunk & 3;
            const char* gh = (const char*)Bb + (size_t)row * brow_bytes + kb + cb * 16;
            asm volatile("cp.async.cg.shared.global [%0], [%1], 16;"
                         :: "r"(sb + TILE_B + row * RSB + cb * 16), "l"(gh));
        }
        #pragma unroll
        for (int j = 0; j < 2; j++) {
            int chunk = tid + j * 256;
            int row = chunk >> 2, cb = chunk & 3;
            const char* gl = (const char*)Bb + (size_t)row * brow_bytes + lo_off + kb + cb * 16;
            asm volatile("cp.async.cg.shared.global [%0], [%1], 16;"
                         :: "r"(sb + 2 * TILE_B + row * RSB + cb * 16), "l"(gl));
        }
        asm volatile("cp.async.commit_group;");
    };

    #pragma unroll
    for (int s = 0; s < 2; s++) load_stage(s, s);

    const uint32_t lrow = (lane & 15);
    const uint32_t lkb  = (lane >> 4) * 16;

    for (int i = 0; i < NKP; i++) {
        asm volatile("cp.async.wait_group 1;");
        __syncthreads();
        int nxt = i + 2;
        if (nxt < NKP) load_stage(nxt, nxt % 3);
        else           asm volatile("cp.async.commit_group;");

        const uint32_t sb = smem_base + (i % 3) * STAGE;
        const uint32_t abase  = sb + (wm * 64) * RSB;
        const uint32_t bhbase = sb + TILE_B     + (wn * 32) * RSB;
        const uint32_t blbase = sb + 2 * TILE_B + (wn * 32) * RSB;

        #pragma unroll
        for (int ks = 0; ks < 2; ks++) {
            uint32_t Af[4][4], Bh[2][4], Bl[2][4];
            #pragma unroll
            for (int mt = 0; mt < 4; mt++)
                LDSM_X4(Af[mt], abase + (mt * 16 + lrow) * RSB + ks * 32 + lkb);
            #pragma unroll
            for (int g = 0; g < 2; g++)
                LDSM_X4(Bh[g], bhbase + (g * 16 + lrow) * RSB + ks * 32 + lkb);
            #pragma unroll
            for (int g = 0; g < 2; g++)
                LDSM_X4(Bl[g], blbase + (g * 16 + lrow) * RSB + ks * 32 + lkb);

            #pragma unroll
            for (int mt = 0; mt < 4; mt++)
                #pragma unroll
                for (int nt = 0; nt < 4; nt++) {
                    uint32_t b2[2] = { Bh[nt >> 1][nt & 1], Bh[nt >> 1][(nt & 1) + 2] };
                    MMA_F16(acc[mt][nt], Af[mt], b2);
                }
            #pragma unroll
            for (int mt = 0; mt < 4; mt++)
                #pragma unroll
                for (int nt = 0; nt < 4; nt++) {
                    uint32_t b2[2] = { Bl[nt >> 1][nt & 1], Bl[nt >> 1][(nt & 1) + 2] };
                    MMA_F16(acc[mt][nt], Af[mt], b2);
                }
        }
    }
    __syncthreads();

    // ---- acc -> smem bounce -> fused coalesced epilogue ----
    float* stile = (float*)smem;               // [128][132]
    const int groupID = lane >> 2, tig = lane & 3;
    #pragma unroll
    for (int mt = 0; mt < 4; mt++) {
        int r0 = wm * 64 + mt * 16 + groupID;
        #pragma unroll
        for (int nt = 0; nt < 4; nt++) {
            int c = wn * 32 + nt * 8 + tig * 2;
            *(float2*)&stile[r0 * 132 + c]       = make_float2(acc[mt][nt][0], acc[mt][nt][1]);
            *(float2*)&stile[(r0 + 8) * 132 + c] = make_float2(acc[mt][nt][2], acc[mt][nt][3]);
        }
    }
    __syncthreads();

    float4 b4 = make_float4(0.f, 0.f, 0.f, 0.f);
    int col = n0 + lane * 4;
    if (HAS_BIAS) b4 = *(const float4*)(bias + col);

    #pragma unroll 4
    for (int rr = 0; rr < 16; rr++) {
        int r = warp * 16 + rr;
        int row = m0 + r;
        float4 v = *(float4*)&stile[r * 132 + lane * 4];
        if (HAS_BIAS) { v.x += b4.x; v.y += b4.y; v.z += b4.z; v.w += b4.w; }
        if (HAS_RES) {
            float4 r4 = *(const float4*)(res + (size_t)row * Nc + col);
            v.x += r4.x; v.y += r4.y; v.z += r4.z; v.w += r4.w;
        }
        *(float4*)(Cf + (size_t)row * Nc + col) = v;
    }
}

// ---------------- chunked scan (== FFT causal conv) ----------------
#define CHUNK 64
#define NCHUNK (SEQ_LEN / CHUNK)

__global__ __launch_bounds__(128) void scan1(const float* __restrict__ proj,
                                             const float* __restrict__ A_log,
                                             float* __restrict__ carry)
{
    int c = blockIdx.x, b = blockIdx.y, s = threadIdx.x;
    float lam = expf(-expf(A_log[s]));
    size_t row0 = (size_t)b * SEQ_LEN + c * CHUNK;
    float y = 0.f;
    #pragma unroll 8
    for (int t = 0; t < CHUNK; t++) {
        const float* p = proj + (row0 + t) * NPROJ;
        y = fmaf(lam, y, p[s] * p[128 + s]);
    }
    carry[(b * NCHUNK + c) * D_STATE + s] = y;
}

__global__ __launch_bounds__(128) void scan2(const float* __restrict__ A_log,
                                             float* __restrict__ carry)
{
    int b = blockIdx.x, s = threadIdx.x;
    float lam64 = expf(-expf(A_log[s]) * (float)CHUNK);
    float S = 0.f;
    for (int c = 0; c < NCHUNK; c++) {
        size_t i = (size_t)(b * NCHUNK + c) * D_STATE + s;
        float f = carry[i];
        carry[i] = S;
        S = fmaf(lam64, S, f);
    }
}

__global__ __launch_bounds__(128) void scan3(const float* __restrict__ proj,
                                             const float* __restrict__ A_log,
                                             const float* __restrict__ carry,
                                             __half* __restrict__ act)
{
    int c = blockIdx.x, b = blockIdx.y, s = threadIdx.x;
    float lam = expf(-expf(A_log[s]));
    float y = carry[(b * NCHUNK + c) * D_STATE + s];
    size_t row0 = (size_t)b * SEQ_LEN + c * CHUNK;
    #pragma unroll 4
    for (int t = 0; t < CHUNK; t++) {
        size_t row = row0 + t;
        const float* p = proj + row * NPROJ;
        y = fmaf(lam, y, p[s] * p[128 + s]);
        act[row * ACTW + D_MODEL + s] = __float2half_rn(y * p[256 + s]);
    }
}

// ---------------- launch ----------------
extern "C" void kernel_launch(void* const* d_in, const int* in_sizes, int n_in,
                              void* d_out, int out_size)
{
    const float* x        = (const float*)d_in[0];
    const float* ln_gamma = (const float*)d_in[1];
    const float* ln_beta  = (const float*)d_in[2];
    const float* W_in     = (const float*)d_in[3];
    const float* b_in     = (const float*)d_in[4];
    const float* W_xs     = (const float*)d_in[5];
    const float* W_B      = (const float*)d_in[6];
    const float* b_B      = (const float*)d_in[7];
    const float* W_C      = (const float*)d_in[8];
    const float* b_C      = (const float*)d_in[9];
    const float* A_log    = (const float*)d_in[10];
    const float* Dv       = (const float*)d_in[11];
    const float* W_so     = (const float*)d_in[12];
    const float* W_out    = (const float*)d_in[13];
    const float* b_out    = (const float*)d_in[14];
    float* out = (float*)d_out;

    __half *p_act, *p_WinA, *p_WsoA, *p_WpB, *p_WdB, *p_WoutB, *p_W4, *p_Wcat;
    float *p_proj, *p_b4, *p_b5, *p_carry;
    cudaGetSymbolAddress((void**)&p_act,   g_act);
    cudaGetSymbolAddress((void**)&p_proj,  g_proj);
    cudaGetSymbolAddress((void**)&p_WinA,  g_WinA);
    cudaGetSymbolAddress((void**)&p_WsoA,  g_WsoA);
    cudaGetSymbolAddress((void**)&p_WpB,   g_WpB);
    cudaGetSymbolAddress((void**)&p_WdB,   g_WdB);
    cudaGetSymbolAddress((void**)&p_WoutB, g_WoutB);
    cudaGetSymbolAddress((void**)&p_W4,    g_W4);
    cudaGetSymbolAddress((void**)&p_Wcat,  g_Wcat);
    cudaGetSymbolAddress((void**)&p_b4,    g_b4);
    cudaGetSymbolAddress((void**)&p_b5,    g_b5);
    cudaGetSymbolAddress((void**)&p_carry, g_carry);

    cudaFuncSetAttribute(bgemm<true, false>, cudaFuncAttributeMaxDynamicSharedMemorySize, GSM);
    cudaFuncSetAttribute(bgemm<true, true >, cudaFuncAttributeMaxDynamicSharedMemorySize, GSM);
    cudaFuncSetAttribute(pgemm, cudaFuncAttributeMaxDynamicSharedMemorySize, PGSM);

    // ---- weight splits ----
    prep_split_A<<<(D_MODEL * D_MODEL + 255) / 256, 256>>>(W_in, p_WinA, D_MODEL, D_MODEL);
    prep_split_A<<<(D_STATE * D_MODEL + 255) / 256, 256>>>(W_so, p_WsoA, D_STATE, D_MODEL);
    prep_split_B<<<(D_MODEL * D_STATE + 255) / 256, 256>>>(W_xs, p_WpB,                             D_MODEL, D_STATE, nullptr);
    prep_split_B<<<(D_MODEL * D_STATE + 255) / 256, 256>>>(W_B,  p_WpB + (size_t)128 * 2 * D_MODEL, D_MODEL, D_STATE, nullptr);
    prep_split_B<<<(D_MODEL * D_STATE + 255) / 256, 256>>>(W_C,  p_WpB + (size_t)256 * 2 * D_MODEL, D_MODEL, D_STATE, nullptr);
    prep_split_B<<<(D_MODEL * D_MODEL + 255) / 256, 256>>>(W_out, p_WdB,   D_MODEL, D_MODEL, Dv);
    prep_split_B<<<(D_MODEL * D_MODEL + 255) / 256, 256>>>(W_out, p_WoutB, D_MODEL, D_MODEL, nullptr);

    // ---- combined weights (3-term precompute GEMMs) ----
    pgemm<<<dim3(NPROJ / PBN, D_MODEL / PBM), 256, PGSM>>>(p_WinA, p_WpB,  D_MODEL, p_W4,   D_MODEL, 0);
    pgemm<<<dim3(D_MODEL / PBN, D_MODEL / PBM), 256, PGSM>>>(p_WinA, p_WdB,  D_MODEL, p_Wcat, KOUT, 0);
    pgemm<<<dim3(D_MODEL / PBN, D_STATE / PBM), 256, PGSM>>>(p_WsoA, p_WoutB, D_MODEL, p_Wcat, KOUT, D_MODEL);

    // ---- combined biases ----
    bias4_k<<<3, 128>>>(b_in, W_xs, W_B, b_B, W_C, b_C, p_b4);
    bias5_k<<<4, 256>>>(b_in, Dv, W_out, b_out, p_b5);

    // ---- LayerNorm -> act[:, 0:1024] ----
    ln_h_kernel<<<ROWS, 256>>>(x, ln_gamma, ln_beta, p_act);

    // ---- proj = xn @ W4 + b4 ----
    bgemm<true, false><<<dim3(NPROJ / BN, ROWS / BM), 256, GSM>>>(
        p_act, ACTW, p_W4, D_MODEL, NPROJ, p_proj, p_b4, nullptr);

    // ---- chunked linear recurrence (== FFT causal conv) -> act[:, 1024:1152] ----
    scan1<<<dim3(NCHUNK, BATCH), 128>>>(p_proj, A_log, p_carry);
    scan2<<<BATCH, 128>>>(A_log, p_carry);
    scan3<<<dim3(NCHUNK, BATCH), 128>>>(p_proj, A_log, p_carry, p_act);

    // ---- out = [xn | ysc] @ Wcat + b5 + x ----
    bgemm<true, true><<<dim3(D_MODEL / BN, ROWS / BM), 256, GSM>>>(
        p_act, ACTW, p_Wcat, KOUT, D_MODEL, out, p_b5, x);
}